// round 13
// baseline (speedup 1.0000x reference)
#include <cuda_runtime.h>
#include <cuda_bf16.h>
#include <cuda_fp16.h>
#include <stdint.h>

#define N_NODES 10000
#define M_TILES 79
#define M_PAD   (M_TILES * 128)     // 10112
#define ROW_WORDS 320
#define USED_WORDS 313
#define D 256
#define MAX_NBR 1024

#define KW 512                      // packed [hi | lo] width
#define NSTEP 12                    // 3 groups x 4 chunks of K=64
#define SROW_B 144                  // padded smem row: 72 bf16 = 144 bytes
#define STILE  (128 * SROW_B)       // 18432 bytes per tile buffer
#define GEMM_SMEM (4 * STILE)       // A0,A1,B0,B1 = 73728

// Scratch (allocation-free rule: __device__ globals)
__device__ uint32_t       g_bitmap[(size_t)N_NODES * ROW_WORDS];   // 12.8 MB
__device__ float          g_dinv[N_NODES];
__device__ __half         g_xwh[(size_t)N_NODES * D];              // fp16 dinv.*(x@W)
__device__ __nv_bfloat16  g_abf[(size_t)M_PAD * KW];               // [m, hi|lo]
__device__ __nv_bfloat16  g_bbf[(size_t)256 * KW];                 // W^T: [n, hi|lo]

__device__ __forceinline__ uint32_t smem_u32(const void* p) {
    uint32_t a;
    asm("{ .reg .u64 t; cvta.to.shared.u64 t, %1; cvt.u32.u64 %0, t; }" : "=r"(a) : "l"(p));
    return a;
}
__device__ __forceinline__ void cp_async16(uint32_t dst, const void* src) {
    asm volatile("cp.async.cg.shared.global [%0], [%1], 16;" :: "r"(dst), "l"(src));
}
__device__ __forceinline__ void ldsm_x4(uint32_t& r0, uint32_t& r1, uint32_t& r2,
                                        uint32_t& r3, uint32_t addr) {
    asm volatile("ldmatrix.sync.aligned.m8n8.x4.shared.b16 {%0,%1,%2,%3}, [%4];"
                 : "=r"(r0), "=r"(r1), "=r"(r2), "=r"(r3) : "r"(addr));
}
#define MMA16816(d, a, b)                                                       \
    asm volatile("mma.sync.aligned.m16n8k16.row.col.f32.bf16.bf16.f32 "         \
                 "{%0,%1,%2,%3}, {%4,%5,%6,%7}, {%8,%9}, {%0,%1,%2,%3};"        \
                 : "+f"((d)[0]), "+f"((d)[1]), "+f"((d)[2]), "+f"((d)[3])       \
                 : "r"((a)[0]), "r"((a)[1]), "r"((a)[2]), "r"((a)[3]),          \
                   "r"((b)[0]), "r"((b)[1]))

// ---------------------------------------------------------------- zero bitmap
__global__ void zero_bitmap_kernel() {
    const size_t total = (size_t)N_NODES * ROW_WORDS / 4;
    uint4* p = (uint4*)g_bitmap;
    uint4 z = make_uint4(0u, 0u, 0u, 0u);
    for (size_t i = (size_t)blockIdx.x * blockDim.x + threadIdx.x; i < total;
         i += (size_t)gridDim.x * blockDim.x)
        p[i] = z;
}

// ------------------------------------------------------------- edge scatter
__global__ void scatter_kernel(const int* __restrict__ ei, int E) {
    int e = blockIdx.x * blockDim.x + threadIdx.x;
    if (e >= E) return;
    int s = ei[e];
    int d = ei[E + e];
    if ((unsigned)s >= N_NODES || (unsigned)d >= N_NODES) return;
    atomicOr(&g_bitmap[(size_t)s * ROW_WORDS + (d >> 5)], 1u << (d & 31));
    atomicOr(&g_bitmap[(size_t)d * ROW_WORDS + (s >> 5)], 1u << (s & 31));
}

// ------------------------------------------------------ degree -> dinv
__global__ void degree_kernel() {
    int i = blockIdx.x * (blockDim.x >> 5) + (threadIdx.x >> 5);
    if (i >= N_NODES) return;
    int lane = threadIdx.x & 31;
    const uint32_t* row = g_bitmap + (size_t)i * ROW_WORDS;
    int s = 0;
    for (int w = lane; w < USED_WORDS; w += 32) s += __popc(row[w]);
    #pragma unroll
    for (int o = 16; o; o >>= 1) s += __shfl_down_sync(0xffffffffu, s, o);
    if (lane == 0) g_dinv[i] = rsqrtf((float)s + 1.0f);
}

// ------------------------------------------------- bf16 hi/lo conversions
__global__ void convert_x_kernel(const float* __restrict__ x) {
    int idx = blockIdx.x * blockDim.x + threadIdx.x;
    if (idx >= M_PAD * 64) return;
    int i = idx >> 6, kq = (idx & 63) * 4;
    float4 a = make_float4(0.f, 0.f, 0.f, 0.f);
    if (i < N_NODES) a = *(const float4*)&x[(size_t)i * D + kq];
    __nv_bfloat162 h0 = __floats2bfloat162_rn(a.x, a.y);
    __nv_bfloat162 h1 = __floats2bfloat162_rn(a.z, a.w);
    float4 r;
    r.x = a.x - __bfloat162float(__low2bfloat16(h0));
    r.y = a.y - __bfloat162float(__high2bfloat16(h0));
    r.z = a.z - __bfloat162float(__low2bfloat16(h1));
    r.w = a.w - __bfloat162float(__high2bfloat16(h1));
    __nv_bfloat162 l0 = __floats2bfloat162_rn(r.x, r.y);
    __nv_bfloat162 l1 = __floats2bfloat162_rn(r.z, r.w);
    __nv_bfloat162* hp = (__nv_bfloat162*)(g_abf + (size_t)i * KW + kq);
    __nv_bfloat162* lp = (__nv_bfloat162*)(g_abf + (size_t)i * KW + 256 + kq);
    hp[0] = h0; hp[1] = h1;
    lp[0] = l0; lp[1] = l1;
}
__global__ void convert_w_kernel(const float* __restrict__ W) {
    int idx = blockIdx.x * blockDim.x + threadIdx.x;
    if (idx >= 256 * 64) return;
    int n = idx >> 6, kq = (idx & 63) * 4;
    float a0 = W[(size_t)(kq + 0) * 256 + n];
    float a1 = W[(size_t)(kq + 1) * 256 + n];
    float a2 = W[(size_t)(kq + 2) * 256 + n];
    float a3 = W[(size_t)(kq + 3) * 256 + n];
    __nv_bfloat162 h0 = __floats2bfloat162_rn(a0, a1);
    __nv_bfloat162 h1 = __floats2bfloat162_rn(a2, a3);
    __nv_bfloat162 l0 = __floats2bfloat162_rn(
        a0 - __bfloat162float(__low2bfloat16(h0)),
        a1 - __bfloat162float(__high2bfloat16(h0)));
    __nv_bfloat162 l1 = __floats2bfloat162_rn(
        a2 - __bfloat162float(__low2bfloat16(h1)),
        a3 - __bfloat162float(__high2bfloat16(h1)));
    __nv_bfloat162* hp = (__nv_bfloat162*)(g_bbf + (size_t)n * KW + kq);
    __nv_bfloat162* lp = (__nv_bfloat162*)(g_bbf + (size_t)n * KW + 256 + kq);
    hp[0] = h0; hp[1] = h1;
    lp[0] = l0; lp[1] = l1;
}

// ---------------------- mma.sync bf16 GEMM: xwh = fp16(dinv .* (x @ W))
__global__ __launch_bounds__(256) void gemm_mma_kernel() {
    extern __shared__ char smem[];
    const uint32_t sb = smem_u32(smem);
    const int t = threadIdx.x;
    const int lane = t & 31, wid = t >> 5;
    const int m0 = blockIdx.y * 128;
    const int n0 = blockIdx.x * 128;
    const int m_off = (wid >> 1) * 32;
    const int n_off = (wid & 1) * 64;

    float acc[2][8][4];
    #pragma unroll
    for (int mi = 0; mi < 2; mi++)
        #pragma unroll
        for (int ni = 0; ni < 8; ni++)
            #pragma unroll
            for (int q = 0; q < 4; q++) acc[mi][ni][q] = 0.f;

    auto fill = [&](int c, int buf) {
        const int g  = c >> 2;
        const int kc = (c & 3) * 64;
        const int a_k = ((g == 1) ? 256 : 0) + kc;
        const int b_k = ((g == 2) ? 256 : 0) + kc;
        const char* asrc = (const char*)g_abf + ((size_t)m0 * KW + a_k) * 2;
        const char* bsrc = (const char*)g_bbf + ((size_t)n0 * KW + b_k) * 2;
        uint32_t adst = sb + buf * STILE;
        uint32_t bdst = sb + 2 * STILE + buf * STILE;
        #pragma unroll
        for (int it = 0; it < 4; it++) {
            int idx = t + it * 256;
            int row = idx >> 3, q = idx & 7;
            uint32_t so = row * SROW_B + q * 16;
            size_t go = (size_t)row * (KW * 2) + q * 16;
            cp_async16(adst + so, asrc + go);
            cp_async16(bdst + so, bsrc + go);
        }
        asm volatile("cp.async.commit_group;" ::: "memory");
    };

    auto compute = [&](int buf) {
        uint32_t abase = sb + buf * STILE;
        uint32_t bbase = sb + 2 * STILE + buf * STILE;
        #pragma unroll
        for (int kk = 0; kk < 4; kk++) {
            uint32_t a[2][4];
            #pragma unroll
            for (int mi = 0; mi < 2; mi++) {
                uint32_t row = m_off + mi * 16 + (lane & 15);
                uint32_t addr = abase + row * SROW_B + kk * 32 + ((lane >> 4) * 16);
                ldsm_x4(a[mi][0], a[mi][1], a[mi][2], a[mi][3], addr);
            }
            uint32_t b[8][2];
            #pragma unroll
            for (int p = 0; p < 4; p++) {
                uint32_t row = n_off + p * 16 + (lane & 7) + ((lane >> 4) << 3);
                uint32_t addr = bbase + row * SROW_B + kk * 32 + (((lane >> 3) & 1) * 16);
                uint32_t r0, r1, r2, r3;
                ldsm_x4(r0, r1, r2, r3, addr);
                b[2 * p][0] = r0; b[2 * p][1] = r1;
                b[2 * p + 1][0] = r2; b[2 * p + 1][1] = r3;
            }
            #pragma unroll
            for (int mi = 0; mi < 2; mi++)
                #pragma unroll
                for (int ni = 0; ni < 8; ni++)
                    MMA16816(acc[mi][ni], a[mi], b[ni]);
        }
    };

    fill(0, 0);
    for (int s = 0; s < NSTEP; s++) {
        const int buf = s & 1;
        if (s + 1 < NSTEP) {
            fill(s + 1, buf ^ 1);
            asm volatile("cp.async.wait_group 1;" ::: "memory");
        } else {
            asm volatile("cp.async.wait_group 0;" ::: "memory");
        }
        __syncthreads();
        compute(buf);
        __syncthreads();
    }

    // Epilogue: d-frag -> dinv-scaled fp16 g_xwh
    const int gid = lane >> 2, t4 = lane & 3;
    #pragma unroll
    for (int mi = 0; mi < 2; mi++) {
        int r0 = m0 + m_off + mi * 16 + gid;
        int r1 = r0 + 8;
        float dv0 = (r0 < N_NODES) ? g_dinv[r0] : 0.f;
        float dv1 = (r1 < N_NODES) ? g_dinv[r1] : 0.f;
        #pragma unroll
        for (int ni = 0; ni < 8; ni++) {
            int col = n0 + n_off + ni * 8 + t4 * 2;
            if (r0 < N_NODES)
                *(__half2*)&g_xwh[(size_t)r0 * 256 + col] =
                    __floats2half2_rn(dv0 * acc[mi][ni][0], dv0 * acc[mi][ni][1]);
            if (r1 < N_NODES)
                *(__half2*)&g_xwh[(size_t)r1 * 256 + col] =
                    __floats2half2_rn(dv1 * acc[mi][ni][2], dv1 * acc[mi][ni][3]);
        }
    }
}

// ------------------------------------------------------ SpMM: out = A_norm @ xwh
// fp16 gather, fp32 accumulate. Thread layout: c = t&31 owns 8 columns
// (16B chunk); s = t>>5 handles neighbors k ≡ s (mod 8). Fixed-order
// reduction over the 8 slices -> replay-deterministic.
__global__ __launch_bounds__(256) void spmm_kernel(float* __restrict__ out) {
    const int i = blockIdx.x;
    const int t = threadIdx.x;
    __shared__ int   s_off[MAX_NBR];      // byte offsets (j << 9)
    __shared__ int   s_warp_tot[8];
    __shared__ int   s_cnt;
    __shared__ float s_red[8][32][8];     // [slice][chunk][col]

    const uint32_t* row = g_bitmap + (size_t)i * ROW_WORDS;
    uint32_t w0 = row[t];
    uint32_t w1 = (t < ROW_WORDS - 256) ? row[t + 256] : 0u;
    int cnt_local = __popc(w0) + __popc(w1);

    int lane = t & 31, wid = t >> 5;
    int v = cnt_local;
    #pragma unroll
    for (int o = 1; o < 32; o <<= 1) {
        int u = __shfl_up_sync(0xffffffffu, v, o);
        if (lane >= o) v += u;
    }
    if (lane == 31) s_warp_tot[wid] = v;
    __syncthreads();
    int base = 0;
    for (int ww = 0; ww < wid; ww++) base += s_warp_tot[ww];
    int offset = base + v - cnt_local;
    if (t == 0) {
        int tot = 0;
        #pragma unroll
        for (int ww = 0; ww < 8; ww++) tot += s_warp_tot[ww];
        s_cnt = tot;
    }
    {
        uint32_t bits = w0;
        int wbase = t * 32;
        while (bits) {
            int b = __ffs(bits) - 1;
            bits &= bits - 1;
            if (offset < MAX_NBR) s_off[offset] = (wbase + b) << 9;
            offset++;
        }
        bits = w1;
        wbase = (t + 256) * 32;
        while (bits) {
            int b = __ffs(bits) - 1;
            bits &= bits - 1;
            if (offset < MAX_NBR) s_off[offset] = (wbase + b) << 9;
            offset++;
        }
    }
    __syncthreads();
    const int cnt = min(s_cnt, MAX_NBR);

    const int c = t & 31;        // 16B chunk: cols [8c, 8c+8)
    const int s = t >> 5;        // neighbor slice (== warp id; uniform per warp)
    const char* xwb = (const char*)g_xwh + (size_t)c * 16;

    float acc[8];
    #pragma unroll
    for (int q = 0; q < 8; q++) acc[q] = 0.f;

    auto add16 = [&](const uint4 vv) {
        const __half2* h = (const __half2*)&vv;
        #pragma unroll
        for (int p = 0; p < 4; p++) {
            float2 f = __half22float2(h[p]);
            acc[2 * p]     += f.x;
            acc[2 * p + 1] += f.y;
        }
    };
    if (s == 0) add16(*(const uint4*)(xwb + ((size_t)i << 9)));   // +I self term
    for (int k = s; k < cnt; k += 8)
        add16(*(const uint4*)(xwb + (size_t)(unsigned)s_off[k]));

    #pragma unroll
    for (int q = 0; q < 8; q++) s_red[s][c][q] = acc[q];
    __syncthreads();

    if (s == 0) {
        const float di = g_dinv[i];
        float r[8];
        #pragma unroll
        for (int q = 0; q < 8; q++) {
            float sum = s_red[0][c][q];
            #pragma unroll
            for (int sl = 1; sl < 8; sl++) sum += s_red[sl][c][q];
            r[q] = di * sum;
        }
        float4* dst = (float4*)&out[(size_t)i * 256 + c * 8];
        dst[0] = make_float4(r[0], r[1], r[2], r[3]);
        dst[1] = make_float4(r[4], r[5], r[6], r[7]);
    }
}

// ---------------------------------------------------------------- launch
extern "C" void kernel_launch(void* const* d_in, const int* in_sizes, int n_in,
                              void* d_out, int out_size) {
    const float* x   = (const float*)d_in[0];
    const int*   ei  = (const int*)d_in[1];
    const float* w   = (const float*)d_in[2];
    float*       out = (float*)d_out;
    const int E = in_sizes[1] / 2;

    cudaFuncSetAttribute(gemm_mma_kernel,
                         cudaFuncAttributeMaxDynamicSharedMemorySize, GEMM_SMEM);

    zero_bitmap_kernel<<<1024, 256>>>();
    scatter_kernel<<<(E + 255) / 256, 256>>>(ei, E);
    degree_kernel<<<(N_NODES + 7) / 8, 256>>>();
    convert_x_kernel<<<(M_PAD * 64 + 255) / 256, 256>>>(x);
    convert_w_kernel<<<(256 * 64 + 255) / 256, 256>>>(w);
    gemm_mma_kernel<<<dim3(2, M_TILES), 256, GEMM_SMEM>>>();
    spmm_kernel<<<N_NODES, 256>>>(out);
}

// round 14
// speedup vs baseline: 1.3375x; 1.3375x over previous
#include <cuda_runtime.h>
#include <cuda_bf16.h>
#include <cuda_fp16.h>
#include <stdint.h>

#define N_NODES 10000
#define M_TILES 79
#define M_PAD   (M_TILES * 128)     // 10112
#define ROW_WORDS 320
#define USED_WORDS 313
#define D 256
#define MAX_NBR 1024

#define KW 512                      // packed [hi | lo] width
#define NSTEP 12                    // 3 groups x 4 chunks of K=64
#define SROW_B 144                  // padded smem row: 72 bf16 = 144 bytes
#define STILE  (128 * SROW_B)       // 18432 bytes per tile buffer
#define GEMM_SMEM (4 * STILE)       // A0,A1,B0,B1 = 73728

// prep kernel block ranges
#define ZB_BLOCKS 3125              // 3125*256 uint4 = 800000 = N_NODES*ROW_WORDS/4
#define CX_BLOCKS 2528              // M_PAD*64/256
#define CW_BLOCKS 64                // 256*64/256
#define PREP_BLOCKS (ZB_BLOCKS + CX_BLOCKS + CW_BLOCKS)

// Scratch (allocation-free rule: __device__ globals)
__device__ uint32_t       g_bitmap[(size_t)N_NODES * ROW_WORDS];   // 12.8 MB
__device__ float          g_dinv[N_NODES];
__device__ __half         g_xwh[(size_t)N_NODES * D];              // fp16 dinv.*(x@W)
__device__ __nv_bfloat16  g_abf[(size_t)M_PAD * KW];               // [m, hi|lo]
__device__ __nv_bfloat16  g_bbf[(size_t)256 * KW];                 // W^T: [n, hi|lo]

__device__ __forceinline__ uint32_t smem_u32(const void* p) {
    uint32_t a;
    asm("{ .reg .u64 t; cvta.to.shared.u64 t, %1; cvt.u32.u64 %0, t; }" : "=r"(a) : "l"(p));
    return a;
}
__device__ __forceinline__ void cp_async16(uint32_t dst, const void* src) {
    asm volatile("cp.async.cg.shared.global [%0], [%1], 16;" :: "r"(dst), "l"(src));
}
__device__ __forceinline__ void ldsm_x4(uint32_t& r0, uint32_t& r1, uint32_t& r2,
                                        uint32_t& r3, uint32_t addr) {
    asm volatile("ldmatrix.sync.aligned.m8n8.x4.shared.b16 {%0,%1,%2,%3}, [%4];"
                 : "=r"(r0), "=r"(r1), "=r"(r2), "=r"(r3) : "r"(addr));
}
#define MMA16816(d, a, b)                                                       \
    asm volatile("mma.sync.aligned.m16n8k16.row.col.f32.bf16.bf16.f32 "         \
                 "{%0,%1,%2,%3}, {%4,%5,%6,%7}, {%8,%9}, {%0,%1,%2,%3};"        \
                 : "+f"((d)[0]), "+f"((d)[1]), "+f"((d)[2]), "+f"((d)[3])       \
                 : "r"((a)[0]), "r"((a)[1]), "r"((a)[2]), "r"((a)[3]),          \
                   "r"((b)[0]), "r"((b)[1]))

// --------------------------------------- prep: zero bitmap + both conversions
__global__ void prep_kernel(const float* __restrict__ x,
                            const float* __restrict__ W) {
    const int b = blockIdx.x;
    const int tt = threadIdx.x;
    if (b < ZB_BLOCKS) {
        // zero bitmap: one uint4 per thread
        size_t i = (size_t)b * 256 + tt;
        ((uint4*)g_bitmap)[i] = make_uint4(0u, 0u, 0u, 0u);
    } else if (b < ZB_BLOCKS + CX_BLOCKS) {
        // convert x -> bf16 hi/lo, row layout [hi(256) | lo(256)]
        int idx = (b - ZB_BLOCKS) * 256 + tt;
        int i = idx >> 6, kq = (idx & 63) * 4;
        float4 a = make_float4(0.f, 0.f, 0.f, 0.f);
        if (i < N_NODES) a = *(const float4*)&x[(size_t)i * D + kq];
        __nv_bfloat162 h0 = __floats2bfloat162_rn(a.x, a.y);
        __nv_bfloat162 h1 = __floats2bfloat162_rn(a.z, a.w);
        __nv_bfloat162 l0 = __floats2bfloat162_rn(
            a.x - __bfloat162float(__low2bfloat16(h0)),
            a.y - __bfloat162float(__high2bfloat16(h0)));
        __nv_bfloat162 l1 = __floats2bfloat162_rn(
            a.z - __bfloat162float(__low2bfloat16(h1)),
            a.w - __bfloat162float(__high2bfloat16(h1)));
        __nv_bfloat162* hp = (__nv_bfloat162*)(g_abf + (size_t)i * KW + kq);
        __nv_bfloat162* lp = (__nv_bfloat162*)(g_abf + (size_t)i * KW + 256 + kq);
        hp[0] = h0; hp[1] = h1;
        lp[0] = l0; lp[1] = l1;
    } else {
        // convert W^T -> bf16 hi/lo, row layout [hi(256) | lo(256)]
        int idx = (b - ZB_BLOCKS - CX_BLOCKS) * 256 + tt;
        int n = idx >> 6, kq = (idx & 63) * 4;
        float a0 = W[(size_t)(kq + 0) * 256 + n];
        float a1 = W[(size_t)(kq + 1) * 256 + n];
        float a2 = W[(size_t)(kq + 2) * 256 + n];
        float a3 = W[(size_t)(kq + 3) * 256 + n];
        __nv_bfloat162 h0 = __floats2bfloat162_rn(a0, a1);
        __nv_bfloat162 h1 = __floats2bfloat162_rn(a2, a3);
        __nv_bfloat162 l0 = __floats2bfloat162_rn(
            a0 - __bfloat162float(__low2bfloat16(h0)),
            a1 - __bfloat162float(__high2bfloat16(h0)));
        __nv_bfloat162 l1 = __floats2bfloat162_rn(
            a2 - __bfloat162float(__low2bfloat16(h1)),
            a3 - __bfloat162float(__high2bfloat16(h1)));
        __nv_bfloat162* hp = (__nv_bfloat162*)(g_bbf + (size_t)n * KW + kq);
        __nv_bfloat162* lp = (__nv_bfloat162*)(g_bbf + (size_t)n * KW + 256 + kq);
        hp[0] = h0; hp[1] = h1;
        lp[0] = l0; lp[1] = l1;
    }
}

// ------------------------------------------------------------- edge scatter
__global__ void scatter_kernel(const int* __restrict__ ei, int E) {
    int e = blockIdx.x * blockDim.x + threadIdx.x;
    if (e >= E) return;
    int s = ei[e];
    int d = ei[E + e];
    if ((unsigned)s >= N_NODES || (unsigned)d >= N_NODES) return;
    atomicOr(&g_bitmap[(size_t)s * ROW_WORDS + (d >> 5)], 1u << (d & 31));
    atomicOr(&g_bitmap[(size_t)d * ROW_WORDS + (s >> 5)], 1u << (s & 31));
}

// ------------------------------------------------------ degree -> dinv
__global__ void degree_kernel() {
    int i = blockIdx.x * (blockDim.x >> 5) + (threadIdx.x >> 5);
    if (i >= N_NODES) return;
    int lane = threadIdx.x & 31;
    const uint32_t* row = g_bitmap + (size_t)i * ROW_WORDS;
    int s = 0;
    for (int w = lane; w < USED_WORDS; w += 32) s += __popc(row[w]);
    #pragma unroll
    for (int o = 16; o; o >>= 1) s += __shfl_down_sync(0xffffffffu, s, o);
    if (lane == 0) g_dinv[i] = rsqrtf((float)s + 1.0f);
}

// ---------------------- mma.sync bf16 GEMM: xwh = fp16(dinv .* (x @ W))
__global__ __launch_bounds__(256) void gemm_mma_kernel() {
    extern __shared__ char smem[];
    const uint32_t sb = smem_u32(smem);
    const int t = threadIdx.x;
    const int lane = t & 31, wid = t >> 5;
    const int m0 = blockIdx.y * 128;
    const int n0 = blockIdx.x * 128;
    const int m_off = (wid >> 1) * 32;
    const int n_off = (wid & 1) * 64;

    float acc[2][8][4];
    #pragma unroll
    for (int mi = 0; mi < 2; mi++)
        #pragma unroll
        for (int ni = 0; ni < 8; ni++)
            #pragma unroll
            for (int q = 0; q < 4; q++) acc[mi][ni][q] = 0.f;

    auto fill = [&](int c, int buf) {
        const int g  = c >> 2;
        const int kc = (c & 3) * 64;
        const int a_k = ((g == 1) ? 256 : 0) + kc;
        const int b_k = ((g == 2) ? 256 : 0) + kc;
        const char* asrc = (const char*)g_abf + ((size_t)m0 * KW + a_k) * 2;
        const char* bsrc = (const char*)g_bbf + ((size_t)n0 * KW + b_k) * 2;
        uint32_t adst = sb + buf * STILE;
        uint32_t bdst = sb + 2 * STILE + buf * STILE;
        #pragma unroll
        for (int it = 0; it < 4; it++) {
            int idx = t + it * 256;
            int row = idx >> 3, q = idx & 7;
            uint32_t so = row * SROW_B + q * 16;
            size_t go = (size_t)row * (KW * 2) + q * 16;
            cp_async16(adst + so, asrc + go);
            cp_async16(bdst + so, bsrc + go);
        }
        asm volatile("cp.async.commit_group;" ::: "memory");
    };

    auto compute = [&](int buf) {
        uint32_t abase = sb + buf * STILE;
        uint32_t bbase = sb + 2 * STILE + buf * STILE;
        #pragma unroll
        for (int kk = 0; kk < 4; kk++) {
            uint32_t a[2][4];
            #pragma unroll
            for (int mi = 0; mi < 2; mi++) {
                uint32_t row = m_off + mi * 16 + (lane & 15);
                uint32_t addr = abase + row * SROW_B + kk * 32 + ((lane >> 4) * 16);
                ldsm_x4(a[mi][0], a[mi][1], a[mi][2], a[mi][3], addr);
            }
            uint32_t b[8][2];
            #pragma unroll
            for (int p = 0; p < 4; p++) {
                uint32_t row = n_off + p * 16 + (lane & 7) + ((lane >> 4) << 3);
                uint32_t addr = bbase + row * SROW_B + kk * 32 + (((lane >> 3) & 1) * 16);
                uint32_t r0, r1, r2, r3;
                ldsm_x4(r0, r1, r2, r3, addr);
                b[2 * p][0] = r0; b[2 * p][1] = r1;
                b[2 * p + 1][0] = r2; b[2 * p + 1][1] = r3;
            }
            #pragma unroll
            for (int mi = 0; mi < 2; mi++)
                #pragma unroll
                for (int ni = 0; ni < 8; ni++)
                    MMA16816(acc[mi][ni], a[mi], b[ni]);
        }
    };

    fill(0, 0);
    for (int s = 0; s < NSTEP; s++) {
        const int buf = s & 1;
        if (s + 1 < NSTEP) {
            fill(s + 1, buf ^ 1);
            asm volatile("cp.async.wait_group 1;" ::: "memory");
        } else {
            asm volatile("cp.async.wait_group 0;" ::: "memory");
        }
        __syncthreads();
        compute(buf);
        __syncthreads();
    }

    // Epilogue: d-frag -> dinv-scaled fp16 g_xwh
    const int gid = lane >> 2, t4 = lane & 3;
    #pragma unroll
    for (int mi = 0; mi < 2; mi++) {
        int r0 = m0 + m_off + mi * 16 + gid;
        int r1 = r0 + 8;
        float dv0 = (r0 < N_NODES) ? g_dinv[r0] : 0.f;
        float dv1 = (r1 < N_NODES) ? g_dinv[r1] : 0.f;
        #pragma unroll
        for (int ni = 0; ni < 8; ni++) {
            int col = n0 + n_off + ni * 8 + t4 * 2;
            if (r0 < N_NODES)
                *(__half2*)&g_xwh[(size_t)r0 * 256 + col] =
                    __floats2half2_rn(dv0 * acc[mi][ni][0], dv0 * acc[mi][ni][1]);
            if (r1 < N_NODES)
                *(__half2*)&g_xwh[(size_t)r1 * 256 + col] =
                    __floats2half2_rn(dv1 * acc[mi][ni][2], dv1 * acc[mi][ni][3]);
        }
    }
}

// ------------------------------------------------------ SpMM: out = A_norm @ xwh
// fp16 gather, fp32 accumulate. c = t&31 owns 8 cols (16B); s = t>>5 handles
// neighbors k ≡ s (mod 8). Reduction buffer padded to 9 floats/chunk so lane
// stride is 36B (9 ⊥ 32) -> conflict-free stores AND reduction reads.
__global__ __launch_bounds__(256) void spmm_kernel(float* __restrict__ out) {
    const int i = blockIdx.x;
    const int t = threadIdx.x;
    __shared__ int   s_off[MAX_NBR];      // byte offsets (j << 9)
    __shared__ int   s_warp_tot[8];
    __shared__ int   s_cnt;
    __shared__ float s_red[8][32][9];     // padded: conflict-free

    const uint32_t* row = g_bitmap + (size_t)i * ROW_WORDS;
    uint32_t w0 = row[t];
    uint32_t w1 = (t < ROW_WORDS - 256) ? row[t + 256] : 0u;
    int cnt_local = __popc(w0) + __popc(w1);

    int lane = t & 31, wid = t >> 5;
    int v = cnt_local;
    #pragma unroll
    for (int o = 1; o < 32; o <<= 1) {
        int u = __shfl_up_sync(0xffffffffu, v, o);
        if (lane >= o) v += u;
    }
    if (lane == 31) s_warp_tot[wid] = v;
    __syncthreads();
    int base = 0;
    for (int ww = 0; ww < wid; ww++) base += s_warp_tot[ww];
    int offset = base + v - cnt_local;
    if (t == 0) {
        int tot = 0;
        #pragma unroll
        for (int ww = 0; ww < 8; ww++) tot += s_warp_tot[ww];
        s_cnt = tot;
    }
    {
        uint32_t bits = w0;
        int wbase = t * 32;
        while (bits) {
            int b = __ffs(bits) - 1;
            bits &= bits - 1;
            if (offset < MAX_NBR) s_off[offset] = (wbase + b) << 9;
            offset++;
        }
        bits = w1;
        wbase = (t + 256) * 32;
        while (bits) {
            int b = __ffs(bits) - 1;
            bits &= bits - 1;
            if (offset < MAX_NBR) s_off[offset] = (wbase + b) << 9;
            offset++;
        }
    }
    __syncthreads();
    const int cnt = min(s_cnt, MAX_NBR);

    const int c = t & 31;        // 16B chunk: cols [8c, 8c+8)
    const int s = t >> 5;        // neighbor slice (uniform per warp)
    const char* xwb = (const char*)g_xwh + (size_t)c * 16;

    float acc[8];
    #pragma unroll
    for (int q = 0; q < 8; q++) acc[q] = 0.f;

    auto add16 = [&](const uint4 vv) {
        const __half2* h = (const __half2*)&vv;
        #pragma unroll
        for (int p = 0; p < 4; p++) {
            float2 f = __half22float2(h[p]);
            acc[2 * p]     += f.x;
            acc[2 * p + 1] += f.y;
        }
    };
    if (s == 0) add16(*(const uint4*)(xwb + ((size_t)i << 9)));   // +I self term
    for (int k = s; k < cnt; k += 8)
        add16(*(const uint4*)(xwb + (size_t)(unsigned)s_off[k]));

    #pragma unroll
    for (int q = 0; q < 8; q++) s_red[s][c][q] = acc[q];
    __syncthreads();

    if (s == 0) {
        const float di = g_dinv[i];
        float r[8];
        #pragma unroll
        for (int q = 0; q < 8; q++) {
            float sum = s_red[0][c][q];
            #pragma unroll
            for (int sl = 1; sl < 8; sl++) sum += s_red[sl][c][q];
            r[q] = di * sum;
        }
        float4* dst = (float4*)&out[(size_t)i * 256 + c * 8];
        dst[0] = make_float4(r[0], r[1], r[2], r[3]);
        dst[1] = make_float4(r[4], r[5], r[6], r[7]);
    }
}

// ---------------------------------------------------------------- launch
extern "C" void kernel_launch(void* const* d_in, const int* in_sizes, int n_in,
                              void* d_out, int out_size) {
    const float* x   = (const float*)d_in[0];
    const int*   ei  = (const int*)d_in[1];
    const float* w   = (const float*)d_in[2];
    float*       out = (float*)d_out;
    const int E = in_sizes[1] / 2;

    cudaFuncSetAttribute(gemm_mma_kernel,
                         cudaFuncAttributeMaxDynamicSharedMemorySize, GEMM_SMEM);

    prep_kernel<<<PREP_BLOCKS, 256>>>(x, w);
    scatter_kernel<<<(E + 255) / 256, 256>>>(ei, E);
    degree_kernel<<<(N_NODES + 7) / 8, 256>>>();
    gemm_mma_kernel<<<dim3(2, M_TILES), 256, GEMM_SMEM>>>();
    spmm_kernel<<<N_NODES, 256>>>(out);
}

// round 15
// speedup vs baseline: 1.5087x; 1.1281x over previous
#include <cuda_runtime.h>
#include <cuda_bf16.h>
#include <cuda_fp16.h>
#include <stdint.h>

#define N_NODES 10000
#define M_TILES 79
#define M_PAD   (M_TILES * 128)     // 10112
#define ROW_WORDS 320
#define USED_WORDS 313
#define D 256
#define MAX_NBR 1024

#define KW 512                      // packed [hi | lo] width
#define NSTEP 12                    // 3 groups x 4 chunks of K=64
#define SROW_B 144                  // padded smem row: 72 bf16 = 144 bytes
#define ATILE  (128 * SROW_B)       // 18432 B
#define BTILE  (64 * SROW_B)        // 9216 B
#define GEMM_SMEM (2 * ATILE + 2 * BTILE)   // 55296

// convert kernel block ranges
#define CX_BLOCKS 2528              // M_PAD*64/256
#define CW_BLOCKS 64                // 256*64/256

// Scratch (allocation-free rule: __device__ globals)
__device__ uint32_t       g_bitmap[(size_t)N_NODES * ROW_WORDS];   // 12.8 MB
__device__ float          g_dinv[N_NODES];
__device__ __half         g_xwh[(size_t)N_NODES * D];              // fp16 x@W (unscaled)
__device__ __nv_bfloat16  g_abf[(size_t)M_PAD * KW];               // [m, hi|lo]
__device__ __nv_bfloat16  g_bbf[(size_t)256 * KW];                 // W^T: [n, hi|lo]

__device__ __forceinline__ uint32_t smem_u32(const void* p) {
    uint32_t a;
    asm("{ .reg .u64 t; cvta.to.shared.u64 t, %1; cvt.u32.u64 %0, t; }" : "=r"(a) : "l"(p));
    return a;
}
__device__ __forceinline__ void cp_async16(uint32_t dst, const void* src) {
    asm volatile("cp.async.cg.shared.global [%0], [%1], 16;" :: "r"(dst), "l"(src));
}
__device__ __forceinline__ void ldsm_x4(uint32_t& r0, uint32_t& r1, uint32_t& r2,
                                        uint32_t& r3, uint32_t addr) {
    asm volatile("ldmatrix.sync.aligned.m8n8.x4.shared.b16 {%0,%1,%2,%3}, [%4];"
                 : "=r"(r0), "=r"(r1), "=r"(r2), "=r"(r3) : "r"(addr));
}
#define MMA16816(d, a, b)                                                       \
    asm volatile("mma.sync.aligned.m16n8k16.row.col.f32.bf16.bf16.f32 "         \
                 "{%0,%1,%2,%3}, {%4,%5,%6,%7}, {%8,%9}, {%0,%1,%2,%3};"        \
                 : "+f"((d)[0]), "+f"((d)[1]), "+f"((d)[2]), "+f"((d)[3])       \
                 : "r"((a)[0]), "r"((a)[1]), "r"((a)[2]), "r"((a)[3]),          \
                   "r"((b)[0]), "r"((b)[1]))

// ---------------------------------------------------------------- zero bitmap
__global__ void zero_bitmap_kernel() {
    size_t i = (size_t)blockIdx.x * 256 + threadIdx.x;
    ((uint4*)g_bitmap)[i] = make_uint4(0u, 0u, 0u, 0u);   // grid sized exactly
}

// --------------------------------------------- bf16 hi/lo conversions (fused)
__global__ void convert_kernel(const float* __restrict__ x,
                               const float* __restrict__ W) {
    const int b = blockIdx.x;
    const int tt = threadIdx.x;
    if (b < CX_BLOCKS) {
        int idx = b * 256 + tt;
        int i = idx >> 6, kq = (idx & 63) * 4;
        float4 a = make_float4(0.f, 0.f, 0.f, 0.f);
        if (i < N_NODES) a = *(const float4*)&x[(size_t)i * D + kq];
        __nv_bfloat162 h0 = __floats2bfloat162_rn(a.x, a.y);
        __nv_bfloat162 h1 = __floats2bfloat162_rn(a.z, a.w);
        __nv_bfloat162 l0 = __floats2bfloat162_rn(
            a.x - __bfloat162float(__low2bfloat16(h0)),
            a.y - __bfloat162float(__high2bfloat16(h0)));
        __nv_bfloat162 l1 = __floats2bfloat162_rn(
            a.z - __bfloat162float(__low2bfloat16(h1)),
            a.w - __bfloat162float(__high2bfloat16(h1)));
        __nv_bfloat162* hp = (__nv_bfloat162*)(g_abf + (size_t)i * KW + kq);
        __nv_bfloat162* lp = (__nv_bfloat162*)(g_abf + (size_t)i * KW + 256 + kq);
        hp[0] = h0; hp[1] = h1;
        lp[0] = l0; lp[1] = l1;
    } else {
        int idx = (b - CX_BLOCKS) * 256 + tt;
        int n = idx >> 6, kq = (idx & 63) * 4;
        float a0 = W[(size_t)(kq + 0) * 256 + n];
        float a1 = W[(size_t)(kq + 1) * 256 + n];
        float a2 = W[(size_t)(kq + 2) * 256 + n];
        float a3 = W[(size_t)(kq + 3) * 256 + n];
        __nv_bfloat162 h0 = __floats2bfloat162_rn(a0, a1);
        __nv_bfloat162 h1 = __floats2bfloat162_rn(a2, a3);
        __nv_bfloat162 l0 = __floats2bfloat162_rn(
            a0 - __bfloat162float(__low2bfloat16(h0)),
            a1 - __bfloat162float(__high2bfloat16(h0)));
        __nv_bfloat162 l1 = __floats2bfloat162_rn(
            a2 - __bfloat162float(__low2bfloat16(h1)),
            a3 - __bfloat162float(__high2bfloat16(h1)));
        __nv_bfloat162* hp = (__nv_bfloat162*)(g_bbf + (size_t)n * KW + kq);
        __nv_bfloat162* lp = (__nv_bfloat162*)(g_bbf + (size_t)n * KW + 256 + kq);
        hp[0] = h0; hp[1] = h1;
        lp[0] = l0; lp[1] = l1;
    }
}

// ------------------------------------------------------------- edge scatter
__global__ void scatter_kernel(const int* __restrict__ ei, int E) {
    int e = blockIdx.x * blockDim.x + threadIdx.x;
    if (e >= E) return;
    int s = ei[e];
    int d = ei[E + e];
    if ((unsigned)s >= N_NODES || (unsigned)d >= N_NODES) return;
    atomicOr(&g_bitmap[(size_t)s * ROW_WORDS + (d >> 5)], 1u << (d & 31));
    atomicOr(&g_bitmap[(size_t)d * ROW_WORDS + (s >> 5)], 1u << (s & 31));
}

// ------------------------------------------------------ degree -> dinv
__global__ void degree_kernel() {
    int i = blockIdx.x * (blockDim.x >> 5) + (threadIdx.x >> 5);
    if (i >= N_NODES) return;
    int lane = threadIdx.x & 31;
    const uint32_t* row = g_bitmap + (size_t)i * ROW_WORDS;
    int s = 0;
    for (int w = lane; w < USED_WORDS; w += 32) s += __popc(row[w]);
    #pragma unroll
    for (int o = 16; o; o >>= 1) s += __shfl_down_sync(0xffffffffu, s, o);
    if (lane == 0) g_dinv[i] = rsqrtf((float)s + 1.0f);
}

// ---------------------- mma.sync bf16 GEMM: xwh = fp16(x @ W), compensated
// CTA 128x64 (grid 4x79 = 316 -> 2 CTA/SM), BK=64, 8 warps (warp tile 32x32).
__global__ __launch_bounds__(256) void gemm_mma_kernel() {
    extern __shared__ char smem[];
    const uint32_t sb = smem_u32(smem);
    const int t = threadIdx.x;
    const int lane = t & 31, wid = t >> 5;
    const int m0 = blockIdx.y * 128;
    const int n0 = blockIdx.x * 64;
    const int m_off = (wid >> 1) * 32;
    const int n_off = (wid & 1) * 32;

    float acc[2][4][4];
    #pragma unroll
    for (int mi = 0; mi < 2; mi++)
        #pragma unroll
        for (int ni = 0; ni < 4; ni++)
            #pragma unroll
            for (int q = 0; q < 4; q++) acc[mi][ni][q] = 0.f;

    auto fill = [&](int c, int buf) {
        const int g  = c >> 2;
        const int kc = (c & 3) * 64;
        const int a_k = ((g == 1) ? 256 : 0) + kc;
        const int b_k = ((g == 2) ? 256 : 0) + kc;
        const char* asrc = (const char*)g_abf + ((size_t)m0 * KW + a_k) * 2;
        const char* bsrc = (const char*)g_bbf + ((size_t)n0 * KW + b_k) * 2;
        uint32_t adst = sb + buf * ATILE;
        uint32_t bdst = sb + 2 * ATILE + buf * BTILE;
        #pragma unroll
        for (int it = 0; it < 4; it++) {
            int idx = t + it * 256;          // 0..1023: A 128 rows x 8 chunks
            int row = idx >> 3, q = idx & 7;
            cp_async16(adst + row * SROW_B + q * 16,
                       asrc + (size_t)row * (KW * 2) + q * 16);
        }
        #pragma unroll
        for (int it = 0; it < 2; it++) {
            int idx = t + it * 256;          // 0..511: B 64 rows x 8 chunks
            int row = idx >> 3, q = idx & 7;
            cp_async16(bdst + row * SROW_B + q * 16,
                       bsrc + (size_t)row * (KW * 2) + q * 16);
        }
        asm volatile("cp.async.commit_group;" ::: "memory");
    };

    auto compute = [&](int buf) {
        uint32_t abase = sb + buf * ATILE;
        uint32_t bbase = sb + 2 * ATILE + buf * BTILE;
        #pragma unroll
        for (int kk = 0; kk < 4; kk++) {
            uint32_t a[2][4];
            #pragma unroll
            for (int mi = 0; mi < 2; mi++) {
                uint32_t row = m_off + mi * 16 + (lane & 15);
                uint32_t addr = abase + row * SROW_B + kk * 32 + ((lane >> 4) * 16);
                ldsm_x4(a[mi][0], a[mi][1], a[mi][2], a[mi][3], addr);
            }
            uint32_t b[4][2];
            #pragma unroll
            for (int p = 0; p < 2; p++) {
                uint32_t row = n_off + p * 16 + (lane & 7) + ((lane >> 4) << 3);
                uint32_t addr = bbase + row * SROW_B + kk * 32 + (((lane >> 3) & 1) * 16);
                uint32_t r0, r1, r2, r3;
                ldsm_x4(r0, r1, r2, r3, addr);
                b[2 * p][0] = r0; b[2 * p][1] = r1;
                b[2 * p + 1][0] = r2; b[2 * p + 1][1] = r3;
            }
            #pragma unroll
            for (int mi = 0; mi < 2; mi++)
                #pragma unroll
                for (int ni = 0; ni < 4; ni++)
                    MMA16816(acc[mi][ni], a[mi], b[ni]);
        }
    };

    fill(0, 0);
    for (int s = 0; s < NSTEP; s++) {
        const int buf = s & 1;
        if (s + 1 < NSTEP) {
            fill(s + 1, buf ^ 1);
            asm volatile("cp.async.wait_group 1;" ::: "memory");
        } else {
            asm volatile("cp.async.wait_group 0;" ::: "memory");
        }
        __syncthreads();
        compute(buf);
        __syncthreads();
    }

    // Epilogue: d-frag -> fp16 g_xwh (no dinv — applied in spmm)
    const int gid = lane >> 2, t4 = lane & 3;
    #pragma unroll
    for (int mi = 0; mi < 2; mi++) {
        int r0 = m0 + m_off + mi * 16 + gid;
        int r1 = r0 + 8;
        #pragma unroll
        for (int ni = 0; ni < 4; ni++) {
            int col = n0 + n_off + ni * 8 + t4 * 2;
            if (r0 < N_NODES)
                *(__half2*)&g_xwh[(size_t)r0 * 256 + col] =
                    __floats2half2_rn(acc[mi][ni][0], acc[mi][ni][1]);
            if (r1 < N_NODES)
                *(__half2*)&g_xwh[(size_t)r1 * 256 + col] =
                    __floats2half2_rn(acc[mi][ni][2], acc[mi][ni][3]);
        }
    }
}

// ------------------------------------------------------ SpMM
// out_i = di * ( sum_j dj * xwh_j  +  di * xwh_i )
// fp16 gather with per-neighbor fp32 coef, fp32 accumulate. Padded reduction
// buffer (9 floats/chunk, 9 ⊥ 32) -> conflict-free.
__global__ __launch_bounds__(256) void spmm_kernel(float* __restrict__ out) {
    const int i = blockIdx.x;
    const int t = threadIdx.x;
    __shared__ int   s_off[MAX_NBR];      // byte offsets (j << 9)
    __shared__ float s_coef[MAX_NBR];     // dinv[j]
    __shared__ int   s_warp_tot[8];
    __shared__ int   s_cnt;
    __shared__ float s_red[8][32][9];

    const uint32_t* row = g_bitmap + (size_t)i * ROW_WORDS;
    uint32_t w0 = row[t];
    uint32_t w1 = (t < ROW_WORDS - 256) ? row[t + 256] : 0u;
    int cnt_local = __popc(w0) + __popc(w1);

    int lane = t & 31, wid = t >> 5;
    int v = cnt_local;
    #pragma unroll
    for (int o = 1; o < 32; o <<= 1) {
        int u = __shfl_up_sync(0xffffffffu, v, o);
        if (lane >= o) v += u;
    }
    if (lane == 31) s_warp_tot[wid] = v;
    __syncthreads();
    int base = 0;
    for (int ww = 0; ww < wid; ww++) base += s_warp_tot[ww];
    int offset = base + v - cnt_local;
    if (t == 0) {
        int tot = 0;
        #pragma unroll
        for (int ww = 0; ww < 8; ww++) tot += s_warp_tot[ww];
        s_cnt = tot;
    }
    {
        uint32_t bits = w0;
        int wbase = t * 32;
        while (bits) {
            int b = __ffs(bits) - 1;
            bits &= bits - 1;
            if (offset < MAX_NBR) s_off[offset] = (wbase + b) << 9;
            offset++;
        }
        bits = w1;
        wbase = (t + 256) * 32;
        while (bits) {
            int b = __ffs(bits) - 1;
            bits &= bits - 1;
            if (offset < MAX_NBR) s_off[offset] = (wbase + b) << 9;
            offset++;
        }
    }
    __syncthreads();
    const int cnt = min(s_cnt, MAX_NBR);
    for (int k = t; k < cnt; k += 256) s_coef[k] = g_dinv[s_off[k] >> 9];
    __syncthreads();

    const int c = t & 31;        // 16B chunk: cols [8c, 8c+8)
    const int s = t >> 5;        // neighbor slice (uniform per warp)
    const char* xwb = (const char*)g_xwh + (size_t)c * 16;

    float acc[8];
    #pragma unroll
    for (int q = 0; q < 8; q++) acc[q] = 0.f;

    auto add16 = [&](float cf, const uint4 vv) {
        const __half2* h = (const __half2*)&vv;
        #pragma unroll
        for (int p = 0; p < 4; p++) {
            float2 f = __half22float2(h[p]);
            acc[2 * p]     += cf * f.x;
            acc[2 * p + 1] += cf * f.y;
        }
    };
    const float di = g_dinv[i];
    if (s == 0) add16(di, *(const uint4*)(xwb + ((size_t)i << 9)));   // +I self
    for (int k = s; k < cnt; k += 8)
        add16(s_coef[k], *(const uint4*)(xwb + (size_t)(unsigned)s_off[k]));

    #pragma unroll
    for (int q = 0; q < 8; q++) s_red[s][c][q] = acc[q];
    __syncthreads();

    if (s == 0) {
        float r[8];
        #pragma unroll
        for (int q = 0; q < 8; q++) {
            float sum = s_red[0][c][q];
            #pragma unroll
            for (int sl = 1; sl < 8; sl++) sum += s_red[sl][c][q];
            r[q] = di * sum;
        }
        float4* dst = (float4*)&out[(size_t)i * 256 + c * 8];
        dst[0] = make_float4(r[0], r[1], r[2], r[3]);
        dst[1] = make_float4(r[4], r[5], r[6], r[7]);
    }
}

// ---------------------------------------------------------------- launch
extern "C" void kernel_launch(void* const* d_in, const int* in_sizes, int n_in,
                              void* d_out, int out_size) {
    const float* x   = (const float*)d_in[0];
    const int*   ei  = (const int*)d_in[1];
    const float* w   = (const float*)d_in[2];
    float*       out = (float*)d_out;
    const int E = in_sizes[1] / 2;

    static cudaStream_t s1 = nullptr;
    static cudaEvent_t e0 = nullptr, e1 = nullptr;
    if (s1 == nullptr) {
        cudaStreamCreateWithFlags(&s1, cudaStreamNonBlocking);
        cudaEventCreateWithFlags(&e0, cudaEventDisableTiming);
        cudaEventCreateWithFlags(&e1, cudaEventDisableTiming);
        cudaFuncSetAttribute(gemm_mma_kernel,
                             cudaFuncAttributeMaxDynamicSharedMemorySize, GEMM_SMEM);
    }

    // fork: chain B (convert -> gemm) on s1, chain A (bitmap/scatter/degree) on 0
    cudaEventRecord(e0, 0);
    cudaStreamWaitEvent(s1, e0, 0);
    convert_kernel<<<CX_BLOCKS + CW_BLOCKS, 256, 0, s1>>>(x, w);
    gemm_mma_kernel<<<dim3(4, M_TILES), 256, GEMM_SMEM, s1>>>();
    cudaEventRecord(e1, s1);

    zero_bitmap_kernel<<<(int)((size_t)N_NODES * ROW_WORDS / 4 / 256), 256>>>();
    scatter_kernel<<<(E + 255) / 256, 256>>>(ei, E);
    degree_kernel<<<(N_NODES + 7) / 8, 256>>>();

    cudaStreamWaitEvent(0, e1, 0);   // join
    spmm_kernel<<<N_NODES, 256>>>(out);
}